// round 4
// baseline (speedup 1.0000x reference)
#include <cuda_runtime.h>

#define NHEAD 8
#define SEQ   4096
#define DH    8
#define PAIRS (SEQ / 2)          // 2048 packed t-pairs per head

// Scratch (__device__ globals; no allocations allowed).
// Pair-packed effective keys (see precompute):
//  g_zA[g*PAIRS+p] = (zx_{2p}, zx_{2p+1}, zy_{2p}, zy_{2p+1})
//  g_zB[g*PAIRS+p] = (zz_{2p}, zz_{2p+1}, zw_{2p}, zw_{2p+1})
// where z_t = SCALE * ( Wq^T Wk x2_t , bq . Wk x2_t )  (4 components)
__device__ float4 g_zA[NHEAD * PAIRS];
__device__ float4 g_zB[NHEAD * PAIRS];
__device__ float  g_v [NHEAD * SEQ * DH];   // v[g][t][h] = Wv x1 + bv

// ---------------------------------------------------------------------------
// Packed f32x2 helpers (Blackwell; ptxas will not auto-fuse these from C++)
// ---------------------------------------------------------------------------
__device__ __forceinline__ unsigned long long fma2(unsigned long long a,
                                                   unsigned long long b,
                                                   unsigned long long c) {
    unsigned long long d;
    asm("fma.rn.f32x2 %0, %1, %2, %3;" : "=l"(d) : "l"(a), "l"(b), "l"(c));
    return d;
}
__device__ __forceinline__ unsigned long long pack2(float x, float y) {
    unsigned long long r;
    asm("mov.b64 %0, {%1, %2};" : "=l"(r) : "f"(x), "f"(y));
    return r;
}
__device__ __forceinline__ void unpack2(unsigned long long v, float& x, float& y) {
    asm("mov.b64 {%0, %1}, %2;" : "=f"(x), "=f"(y) : "l"(v));
}

// ---------------------------------------------------------------------------
// Precompute: one thread per (g, pair p) -> writes packed zA/zB and v rows.
// ---------------------------------------------------------------------------
__device__ __forceinline__ float4 eff_key(const float X2[3],
                                          const float* __restrict__ Wq,
                                          const float* __restrict__ bq,
                                          const float* __restrict__ Wk) {
    const float SCALEF = 1448.1546878700492f;  // 2^10.5
    float y0 = 0.f, y1 = 0.f, y2 = 0.f, w = 0.f;
#pragma unroll
    for (int h = 0; h < 8; h++) {
        float u = fmaf(Wk[h * 3 + 0], X2[0],
                  fmaf(Wk[h * 3 + 1], X2[1], Wk[h * 3 + 2] * X2[2]));
        y0 = fmaf(Wq[h * 3 + 0], u, y0);
        y1 = fmaf(Wq[h * 3 + 1], u, y1);
        y2 = fmaf(Wq[h * 3 + 2], u, y2);
        w  = fmaf(bq[h], u, w);
    }
    return make_float4(SCALEF * y0, SCALEF * y1, SCALEF * y2, SCALEF * w);
}

__global__ void precompute_kernel(const float* __restrict__ x1,
                                  const float* __restrict__ x2,
                                  const float* __restrict__ Wq,
                                  const float* __restrict__ bq,
                                  const float* __restrict__ Wk,
                                  const float* __restrict__ Wv,
                                  const float* __restrict__ bv) {
    int i = blockIdx.x * blockDim.x + threadIdx.x;   // i = g*PAIRS + p
    if (i >= NHEAD * PAIRS) return;
    const int g = i >> 11;
    const int p = i & (PAIRS - 1);
    const int r0 = g * SEQ + 2 * p;                  // row index of t = 2p

    float X2a[3], X2b[3], X1a[3], X1b[3];
#pragma unroll
    for (int j = 0; j < 3; j++) {
        X2a[j] = x2[r0 * 3 + j];       X2b[j] = x2[(r0 + 1) * 3 + j];
        X1a[j] = x1[r0 * 3 + j];       X1b[j] = x1[(r0 + 1) * 3 + j];
    }
    const float4 za = eff_key(X2a, Wq, bq, Wk);
    const float4 zb = eff_key(X2b, Wq, bq, Wk);
    g_zA[i] = make_float4(za.x, zb.x, za.y, zb.y);
    g_zB[i] = make_float4(za.z, zb.z, za.w, zb.w);

#pragma unroll
    for (int h = 0; h < 8; h++) {
        g_v[(size_t)r0 * 8 + h] =
            fmaf(Wv[h * 3 + 0], X1a[0], fmaf(Wv[h * 3 + 1], X1a[1],
            fmaf(Wv[h * 3 + 2], X1a[2], bv[h])));
        g_v[(size_t)(r0 + 1) * 8 + h] =
            fmaf(Wv[h * 3 + 0], X1b[0], fmaf(Wv[h * 3 + 1], X1b[1],
            fmaf(Wv[h * 3 + 2], X1b[2], bv[h])));
    }
}

// ---------------------------------------------------------------------------
// Threefry2x32, partitionable mode: word(i) = x0^x1 of counter (0, i),
// key (0, 42). keep <=> MSB == 0.
// ---------------------------------------------------------------------------
__device__ __forceinline__ unsigned rotl32(unsigned x, int r) {
    return __funnelshift_l(x, x, r);
}
__device__ __forceinline__ unsigned threefry_word(unsigned idx) {
    const unsigned K1 = 42u;
    const unsigned K2 = 0x1BD11BF0u;
    unsigned x0 = 0u;
    unsigned x1 = idx + K1;
#define TF_R(r)  { x0 += x1; x1 = rotl32(x1, r); x1 ^= x0; }
#define TF_G(a,b,c,d,j0,j1) TF_R(a) TF_R(b) TF_R(c) TF_R(d) x0 += (j0); x1 += (j1);
    TF_G(13, 15, 26,  6, K1,       K2 + 1u)
    TF_G(17, 29, 16, 24, K2,       0u + 2u)
    TF_G(13, 15, 26,  6, 0u,       K1 + 3u)
    TF_G(17, 29, 16, 24, K1,       K2 + 4u)
    TF_G(13, 15, 26,  6, K2,       0u + 5u)
#undef TF_G
#undef TF_R
    return x0 ^ x1;
}

// ---------------------------------------------------------------------------
// Main kernel: 4-lane quad per (g, s) row. Lane q scans t in [q*1024, q*1024+1024)
// with packed f32x2 scores, online softmax with lazy rare path, then quad
// shfl-merge. Block = 256 threads = 64 rows; smem = packed z for head g (64 KB).
// ---------------------------------------------------------------------------
__global__ void __launch_bounds__(256) attn_kernel(const float* __restrict__ x1,
                                                   float* __restrict__ out) {
    extern __shared__ float4 zs[];             // [0,2048) = zA, [2048,4096) = zB
    const int g = blockIdx.y;

    for (int i = threadIdx.x; i < PAIRS; i += blockDim.x) {
        zs[i]         = g_zA[g * PAIRS + i];
        zs[PAIRS + i] = g_zB[g * PAIRS + i];
    }
    __syncthreads();

    const int q   = threadIdx.x & 3;                       // quad lane
    const int s   = blockIdx.x * 64 + (threadIdx.x >> 2);  // row within head
    const int row = g * SEQ + s;

    const float a = x1[row * 3 + 0];
    const float b = x1[row * 3 + 1];
    const float c = x1[row * 3 + 2];
    const unsigned long long aa = pack2(a, a);
    const unsigned long long bb = pack2(b, b);
    const unsigned long long cc = pack2(c, c);

    const unsigned rowbase = ((unsigned)row << 12) + (unsigned)(q << 10);
    const float* vg = g_v + ((size_t)g * SEQ + (size_t)(q << 10)) * DH;

    // This lane's quarter of the packed arrays: 512 pairs.
    // NOTE: ulonglong2 is 16 B == one float4, so zB starts at +PAIRS elements.
    const ulonglong2* ZA = reinterpret_cast<const ulonglong2*>(zs) + q * 512;
    const ulonglong2* ZB = ZA + PAIRS;         // zB region, same quarter offset

    float m = -3.0e38f, l = 0.0f;
    float acc0 = 0.f, acc1 = 0.f, acc2 = 0.f, acc3 = 0.f;
    float acc4 = 0.f, acc5 = 0.f, acc6 = 0.f, acc7 = 0.f;

    for (int p = 0; p < 512; p += 4) {         // 8 t's per iteration
        const ulonglong2 A0 = ZA[p + 0], B0 = ZB[p + 0];
        const ulonglong2 A1 = ZA[p + 1], B1 = ZB[p + 1];
        const ulonglong2 A2 = ZA[p + 2], B2 = ZB[p + 2];
        const ulonglong2 A3 = ZA[p + 3], B3 = ZB[p + 3];
        const unsigned long long S0 = fma2(aa, A0.x, fma2(bb, A0.y, fma2(cc, B0.x, B0.y)));
        const unsigned long long S1 = fma2(aa, A1.x, fma2(bb, A1.y, fma2(cc, B1.x, B1.y)));
        const unsigned long long S2 = fma2(aa, A2.x, fma2(bb, A2.y, fma2(cc, B2.x, B2.y)));
        const unsigned long long S3 = fma2(aa, A3.x, fma2(bb, A3.y, fma2(cc, B3.x, B3.y)));
        float s0, s1, s2, s3, s4, s5, s6, s7;
        unpack2(S0, s0, s1);
        unpack2(S1, s2, s3);
        unpack2(S2, s4, s5);
        unpack2(S3, s6, s7);
        const float pm = fmaxf(fmaxf(fmaxf(s0, s1), fmaxf(s2, s3)),
                               fmaxf(fmaxf(s4, s5), fmaxf(s6, s7)));

        if (pm > m - 25.0f) {                  // cold path: ~7-10 hits per lane
            const float sv[8] = {s0, s1, s2, s3, s4, s5, s6, s7};
#pragma unroll
            for (int j = 0; j < 8; j++) {
                const float sj = sv[j];
                if (sj > m - 25.0f) {
                    float pr;
                    if (sj > m) {
                        const float f = __expf(m - sj);
                        l *= f;
                        acc0 *= f; acc1 *= f; acc2 *= f; acc3 *= f;
                        acc4 *= f; acc5 *= f; acc6 *= f; acc7 *= f;
                        m = sj;
                        pr = 1.0f;
                    } else {
                        pr = __expf(sj - m);
                    }
                    l += pr;   // denominator: all surviving-exp terms (mask-free)
                    const int tloc = 2 * p + j;
                    const unsigned wbits = threefry_word(rowbase + (unsigned)tloc);
                    if (!(wbits & 0x80000000u)) {          // keep (u < 0.5)
                        const float4* vp =
                            reinterpret_cast<const float4*>(vg + (size_t)tloc * DH);
                        const float4 va = vp[0];
                        const float4 vb = vp[1];
                        acc0 = fmaf(pr, va.x, acc0);
                        acc1 = fmaf(pr, va.y, acc1);
                        acc2 = fmaf(pr, va.z, acc2);
                        acc3 = fmaf(pr, va.w, acc3);
                        acc4 = fmaf(pr, vb.x, acc4);
                        acc5 = fmaf(pr, vb.y, acc5);
                        acc6 = fmaf(pr, vb.z, acc6);
                        acc7 = fmaf(pr, vb.w, acc7);
                    }
                }
            }
        }
    }

    // ---- merge the 4 partial online-softmax states within the quad ----
    float M = m;
    M = fmaxf(M, __shfl_xor_sync(0xffffffffu, M, 1));
    M = fmaxf(M, __shfl_xor_sync(0xffffffffu, M, 2));
    const float f = __expf(m - M);
    l *= f;
    acc0 *= f; acc1 *= f; acc2 *= f; acc3 *= f;
    acc4 *= f; acc5 *= f; acc6 *= f; acc7 *= f;
#pragma unroll
    for (int d = 1; d <= 2; d <<= 1) {
        l    += __shfl_xor_sync(0xffffffffu, l,    d);
        acc0 += __shfl_xor_sync(0xffffffffu, acc0, d);
        acc1 += __shfl_xor_sync(0xffffffffu, acc1, d);
        acc2 += __shfl_xor_sync(0xffffffffu, acc2, d);
        acc3 += __shfl_xor_sync(0xffffffffu, acc3, d);
        acc4 += __shfl_xor_sync(0xffffffffu, acc4, d);
        acc5 += __shfl_xor_sync(0xffffffffu, acc5, d);
        acc6 += __shfl_xor_sync(0xffffffffu, acc6, d);
        acc7 += __shfl_xor_sync(0xffffffffu, acc7, d);
    }

    // out = (2 / l) * acc ; lane q writes components [2q, 2q+1] (coalesced 32B/quad)
    const float inv = 2.0f / l;
    const float oc[8] = {acc0 * inv, acc1 * inv, acc2 * inv, acc3 * inv,
                         acc4 * inv, acc5 * inv, acc6 * inv, acc7 * inv};
    float2* op = reinterpret_cast<float2*>(out + (size_t)row * DH);
    op[q] = make_float2(oc[2 * q], oc[2 * q + 1]);
}

// ---------------------------------------------------------------------------
extern "C" void kernel_launch(void* const* d_in, const int* in_sizes, int n_in,
                              void* d_out, int out_size) {
    const float* x1 = (const float*)d_in[0];
    const float* x2 = (const float*)d_in[1];
    const float* Wq = (const float*)d_in[2];
    const float* bq = (const float*)d_in[3];
    const float* Wk = (const float*)d_in[4];
    // d_in[5] = bk: per-row constant -> cancels in softmax
    const float* Wv = (const float*)d_in[6];
    const float* bv = (const float*)d_in[7];
    float* out = (float*)d_out;

    precompute_kernel<<<(NHEAD * PAIRS + 255) / 256, 256>>>(x1, x2, Wq, bq, Wk, Wv, bv);

    const int smem = 2 * PAIRS * (int)sizeof(float4);   // 64 KB
    cudaFuncSetAttribute(attn_kernel, cudaFuncAttributeMaxDynamicSharedMemorySize, smem);
    dim3 grid(SEQ / 64, NHEAD);
    attn_kernel<<<grid, 256, smem>>>(x1, out);
}

// round 5
// speedup vs baseline: 2.5052x; 2.5052x over previous
#include <cuda_runtime.h>

#define NHEAD 8
#define SEQ   4096
#define DH    8
#define PAIRS (SEQ / 2)          // 2048 packed t-pairs per head

// Scratch (__device__ globals; no allocations allowed).
// INTERLEAVED pair-packed effective keys: pair p_g of head g lives at index
//   g*PAIRS + (p_g & 511)*4 + (p_g >> 9)
// so that quad lane q (owning pairs [q*512,(q+1)*512)) reads zs[p*4+q]:
// the quad's 4 reads are 64 B contiguous -> conflict-free smem.
//  zA word: (zx_t, zx_{t+1}, zy_t, zy_{t+1}),  zB word: (zz_t, zz_{t+1}, zw_t, zw_{t+1})
// where z_t = SCALE * ( Wq^T Wk x2_t , bq . Wk x2_t ).
__device__ float4 g_zA[NHEAD * PAIRS];
__device__ float4 g_zB[NHEAD * PAIRS];
__device__ float  g_v [NHEAD * SEQ * DH];   // v[g][t][h] = Wv x1 + bv

// ---------------------------------------------------------------------------
// Packed f32x2 helpers (Blackwell; ptxas will not auto-fuse these from C++)
// ---------------------------------------------------------------------------
__device__ __forceinline__ unsigned long long fma2(unsigned long long a,
                                                   unsigned long long b,
                                                   unsigned long long c) {
    unsigned long long d;
    asm("fma.rn.f32x2 %0, %1, %2, %3;" : "=l"(d) : "l"(a), "l"(b), "l"(c));
    return d;
}
__device__ __forceinline__ unsigned long long pack2(float x, float y) {
    unsigned long long r;
    asm("mov.b64 %0, {%1, %2};" : "=l"(r) : "f"(x), "f"(y));
    return r;
}
__device__ __forceinline__ void unpack2(unsigned long long v, float& x, float& y) {
    asm("mov.b64 {%0, %1}, %2;" : "=f"(x), "=f"(y) : "l"(v));
}

// ---------------------------------------------------------------------------
// Precompute: one thread per (g, pair p) -> writes interleaved zA/zB + v rows.
// ---------------------------------------------------------------------------
__device__ __forceinline__ float4 eff_key(const float X2[3],
                                          const float* __restrict__ Wq,
                                          const float* __restrict__ bq,
                                          const float* __restrict__ Wk) {
    const float SCALEF = 1448.1546878700492f;  // 2^10.5
    float y0 = 0.f, y1 = 0.f, y2 = 0.f, w = 0.f;
#pragma unroll
    for (int h = 0; h < 8; h++) {
        float u = fmaf(Wk[h * 3 + 0], X2[0],
                  fmaf(Wk[h * 3 + 1], X2[1], Wk[h * 3 + 2] * X2[2]));
        y0 = fmaf(Wq[h * 3 + 0], u, y0);
        y1 = fmaf(Wq[h * 3 + 1], u, y1);
        y2 = fmaf(Wq[h * 3 + 2], u, y2);
        w  = fmaf(bq[h], u, w);
    }
    return make_float4(SCALEF * y0, SCALEF * y1, SCALEF * y2, SCALEF * w);
}

__global__ void precompute_kernel(const float* __restrict__ x1,
                                  const float* __restrict__ x2,
                                  const float* __restrict__ Wq,
                                  const float* __restrict__ bq,
                                  const float* __restrict__ Wk,
                                  const float* __restrict__ Wv,
                                  const float* __restrict__ bv) {
    int i = blockIdx.x * blockDim.x + threadIdx.x;   // i = g*PAIRS + p
    if (i >= NHEAD * PAIRS) return;
    const int g = i >> 11;
    const int p = i & (PAIRS - 1);
    const int r0 = g * SEQ + 2 * p;                  // row index of t = 2p

    float X2a[3], X2b[3], X1a[3], X1b[3];
#pragma unroll
    for (int j = 0; j < 3; j++) {
        X2a[j] = x2[r0 * 3 + j];       X2b[j] = x2[(r0 + 1) * 3 + j];
        X1a[j] = x1[r0 * 3 + j];       X1b[j] = x1[(r0 + 1) * 3 + j];
    }
    const float4 za = eff_key(X2a, Wq, bq, Wk);
    const float4 zb = eff_key(X2b, Wq, bq, Wk);

    const int dst = g * PAIRS + ((p & 511) << 2) + (p >> 9);   // interleaved
    g_zA[dst] = make_float4(za.x, zb.x, za.y, zb.y);
    g_zB[dst] = make_float4(za.z, zb.z, za.w, zb.w);

#pragma unroll
    for (int h = 0; h < 8; h++) {
        g_v[(size_t)r0 * 8 + h] =
            fmaf(Wv[h * 3 + 0], X1a[0], fmaf(Wv[h * 3 + 1], X1a[1],
            fmaf(Wv[h * 3 + 2], X1a[2], bv[h])));
        g_v[(size_t)(r0 + 1) * 8 + h] =
            fmaf(Wv[h * 3 + 0], X1b[0], fmaf(Wv[h * 3 + 1], X1b[1],
            fmaf(Wv[h * 3 + 2], X1b[2], bv[h])));
    }
}

// ---------------------------------------------------------------------------
// Threefry2x32, partitionable mode: word(i) = x0^x1 of counter (0, i),
// key (0, 42). keep <=> MSB == 0.
// ---------------------------------------------------------------------------
__device__ __forceinline__ unsigned rotl32(unsigned x, int r) {
    return __funnelshift_l(x, x, r);
}
__device__ __forceinline__ unsigned threefry_word(unsigned idx) {
    const unsigned K1 = 42u;
    const unsigned K2 = 0x1BD11BF0u;
    unsigned x0 = 0u;
    unsigned x1 = idx + K1;
#define TF_R(r)  { x0 += x1; x1 = rotl32(x1, r); x1 ^= x0; }
#define TF_G(a,b,c,d,j0,j1) TF_R(a) TF_R(b) TF_R(c) TF_R(d) x0 += (j0); x1 += (j1);
    TF_G(13, 15, 26,  6, K1,       K2 + 1u)
    TF_G(17, 29, 16, 24, K2,       0u + 2u)
    TF_G(13, 15, 26,  6, 0u,       K1 + 3u)
    TF_G(17, 29, 16, 24, K1,       K2 + 4u)
    TF_G(13, 15, 26,  6, K2,       0u + 5u)
#undef TF_G
#undef TF_R
    return x0 ^ x1;
}

// ---------------------------------------------------------------------------
// Main kernel: 4-lane quad per (g, s) row; lane q scans t in [q*1024, (q+1)*1024)
// through the interleaved smem image (quad reads = contiguous 64 B, conflict-
// free). Online softmax with lazy rare path, then quad shfl-merge.
// Block = 256 threads = 64 rows; smem = packed z for head g (64 KB).
// ---------------------------------------------------------------------------
__global__ void __launch_bounds__(256) attn_kernel(const float* __restrict__ x1,
                                                   float* __restrict__ out) {
    extern __shared__ float4 zs[];             // [0,2048) = zA, [2048,4096) = zB
    const int g = blockIdx.y;

    for (int i = threadIdx.x; i < PAIRS; i += blockDim.x) {
        zs[i]         = g_zA[g * PAIRS + i];   // linear copy keeps interleave
        zs[PAIRS + i] = g_zB[g * PAIRS + i];
    }
    __syncthreads();

    const int q   = threadIdx.x & 3;                       // quad lane
    const int s   = blockIdx.x * 64 + (threadIdx.x >> 2);  // row within head
    const int row = g * SEQ + s;

    const float a = x1[row * 3 + 0];
    const float b = x1[row * 3 + 1];
    const float c = x1[row * 3 + 2];
    const unsigned long long aa = pack2(a, a);
    const unsigned long long bb = pack2(b, b);
    const unsigned long long cc = pack2(c, c);

    const unsigned rowbase = ((unsigned)row << 12) + (unsigned)(q << 10);
    const float* vg = g_v + ((size_t)g * SEQ + (size_t)(q << 10)) * DH;

    // Interleaved streams: lane q's local pair p lives at element p*4 + q.
    const ulonglong2* ZA = reinterpret_cast<const ulonglong2*>(zs) + q;
    const ulonglong2* ZB = ZA + PAIRS;

    float m = -3.0e38f, l = 0.0f;
    float acc0 = 0.f, acc1 = 0.f, acc2 = 0.f, acc3 = 0.f;
    float acc4 = 0.f, acc5 = 0.f, acc6 = 0.f, acc7 = 0.f;

    for (int p = 0; p < 512; p += 4) {         // 8 t's per iteration
        const ulonglong2 A0 = ZA[(p + 0) << 2], B0 = ZB[(p + 0) << 2];
        const ulonglong2 A1 = ZA[(p + 1) << 2], B1 = ZB[(p + 1) << 2];
        const ulonglong2 A2 = ZA[(p + 2) << 2], B2 = ZB[(p + 2) << 2];
        const ulonglong2 A3 = ZA[(p + 3) << 2], B3 = ZB[(p + 3) << 2];
        const unsigned long long S0 = fma2(aa, A0.x, fma2(bb, A0.y, fma2(cc, B0.x, B0.y)));
        const unsigned long long S1 = fma2(aa, A1.x, fma2(bb, A1.y, fma2(cc, B1.x, B1.y)));
        const unsigned long long S2 = fma2(aa, A2.x, fma2(bb, A2.y, fma2(cc, B2.x, B2.y)));
        const unsigned long long S3 = fma2(aa, A3.x, fma2(bb, A3.y, fma2(cc, B3.x, B3.y)));
        float s0, s1, s2, s3, s4, s5, s6, s7;
        unpack2(S0, s0, s1);
        unpack2(S1, s2, s3);
        unpack2(S2, s4, s5);
        unpack2(S3, s6, s7);
        const float pm = fmaxf(fmaxf(fmaxf(s0, s1), fmaxf(s2, s3)),
                               fmaxf(fmaxf(s4, s5), fmaxf(s6, s7)));

        if (pm > m - 25.0f) {                  // cold path: ~7-10 hits per lane
            const float sv[8] = {s0, s1, s2, s3, s4, s5, s6, s7};
#pragma unroll
            for (int j = 0; j < 8; j++) {
                const float sj = sv[j];
                if (sj > m - 25.0f) {
                    float pr;
                    if (sj > m) {
                        const float f = __expf(m - sj);
                        l *= f;
                        acc0 *= f; acc1 *= f; acc2 *= f; acc3 *= f;
                        acc4 *= f; acc5 *= f; acc6 *= f; acc7 *= f;
                        m = sj;
                        pr = 1.0f;
                    } else {
                        pr = __expf(sj - m);
                    }
                    l += pr;   // denominator: all surviving-exp terms (mask-free)
                    const int tloc = 2 * p + j;
                    const unsigned wbits = threefry_word(rowbase + (unsigned)tloc);
                    if (!(wbits & 0x80000000u)) {          // keep (u < 0.5)
                        const float4* vp =
                            reinterpret_cast<const float4*>(vg + (size_t)tloc * DH);
                        const float4 va = vp[0];
                        const float4 vb = vp[1];
                        acc0 = fmaf(pr, va.x, acc0);
                        acc1 = fmaf(pr, va.y, acc1);
                        acc2 = fmaf(pr, va.z, acc2);
                        acc3 = fmaf(pr, va.w, acc3);
                        acc4 = fmaf(pr, vb.x, acc4);
                        acc5 = fmaf(pr, vb.y, acc5);
                        acc6 = fmaf(pr, vb.z, acc6);
                        acc7 = fmaf(pr, vb.w, acc7);
                    }
                }
            }
        }
    }

    // ---- merge the 4 partial online-softmax states within the quad ----
    float M = m;
    M = fmaxf(M, __shfl_xor_sync(0xffffffffu, M, 1));
    M = fmaxf(M, __shfl_xor_sync(0xffffffffu, M, 2));
    const float f = __expf(m - M);
    l *= f;
    acc0 *= f; acc1 *= f; acc2 *= f; acc3 *= f;
    acc4 *= f; acc5 *= f; acc6 *= f; acc7 *= f;
#pragma unroll
    for (int d = 1; d <= 2; d <<= 1) {
        l    += __shfl_xor_sync(0xffffffffu, l,    d);
        acc0 += __shfl_xor_sync(0xffffffffu, acc0, d);
        acc1 += __shfl_xor_sync(0xffffffffu, acc1, d);
        acc2 += __shfl_xor_sync(0xffffffffu, acc2, d);
        acc3 += __shfl_xor_sync(0xffffffffu, acc3, d);
        acc4 += __shfl_xor_sync(0xffffffffu, acc4, d);
        acc5 += __shfl_xor_sync(0xffffffffu, acc5, d);
        acc6 += __shfl_xor_sync(0xffffffffu, acc6, d);
        acc7 += __shfl_xor_sync(0xffffffffu, acc7, d);
    }

    // out = (2 / l) * acc ; lane q writes components [2q, 2q+1] (coalesced)
    const float inv = 2.0f / l;
    const float oc[8] = {acc0 * inv, acc1 * inv, acc2 * inv, acc3 * inv,
                         acc4 * inv, acc5 * inv, acc6 * inv, acc7 * inv};
    float2* op = reinterpret_cast<float2*>(out + (size_t)row * DH);
    op[q] = make_float2(oc[2 * q], oc[2 * q + 1]);
}

// ---------------------------------------------------------------------------
extern "C" void kernel_launch(void* const* d_in, const int* in_sizes, int n_in,
                              void* d_out, int out_size) {
    const float* x1 = (const float*)d_in[0];
    const float* x2 = (const float*)d_in[1];
    const float* Wq = (const float*)d_in[2];
    const float* bq = (const float*)d_in[3];
    const float* Wk = (const float*)d_in[4];
    // d_in[5] = bk: per-row constant -> cancels in softmax
    const float* Wv = (const float*)d_in[6];
    const float* bv = (const float*)d_in[7];
    float* out = (float*)d_out;

    precompute_kernel<<<(NHEAD * PAIRS + 255) / 256, 256>>>(x1, x2, Wq, bq, Wk, Wv, bv);

    const int smem = 2 * PAIRS * (int)sizeof(float4);   // 64 KB
    cudaFuncSetAttribute(attn_kernel, cudaFuncAttributeMaxDynamicSharedMemorySize, smem);
    dim3 grid(SEQ / 64, NHEAD);
    attn_kernel<<<grid, 256, smem>>>(x1, out);
}

// round 6
// speedup vs baseline: 3.4842x; 1.3908x over previous
#include <cuda_runtime.h>

#define NHEAD 8
#define SEQ   4096
#define DH    8
#define PAIRS (SEQ / 2)          // 2048 packed t-pairs per head
#define CAP   16                 // deferred-entry buffer slots per thread
#define WIN   20.0f              // softmax window: dropped terms < 4096*e^-20 ~ 8e-6

// Scratch (__device__ globals; no allocations allowed).
// INTERLEAVED pair-packed effective keys: pair p_g of head g lives at index
//   g*PAIRS + (p_g & 511)*4 + (p_g >> 9)
// so quad lane q (owning pairs [q*512,(q+1)*512)) reads zs[p*4+q]: the quad's
// 4 reads are 64 B contiguous + 8-row broadcast -> conflict-free smem.
//  zA word: (zx_t, zx_{t+1}, zy_t, zy_{t+1}),  zB word: (zz_t, zz_{t+1}, zw_t, zw_{t+1})
// where z_t = SCALE * ( Wq^T Wk x2_t , bq . Wk x2_t ).
__device__ float4 g_zA[NHEAD * PAIRS];
__device__ float4 g_zB[NHEAD * PAIRS];
__device__ float  g_v [NHEAD * SEQ * DH];   // v[g][t][h] = Wv x1 + bv

// ---------------------------------------------------------------------------
// Packed f32x2 helpers
// ---------------------------------------------------------------------------
__device__ __forceinline__ unsigned long long fma2(unsigned long long a,
                                                   unsigned long long b,
                                                   unsigned long long c) {
    unsigned long long d;
    asm("fma.rn.f32x2 %0, %1, %2, %3;" : "=l"(d) : "l"(a), "l"(b), "l"(c));
    return d;
}
__device__ __forceinline__ unsigned long long pack2(float x, float y) {
    unsigned long long r;
    asm("mov.b64 %0, {%1, %2};" : "=l"(r) : "f"(x), "f"(y));
    return r;
}
__device__ __forceinline__ void unpack2(unsigned long long v, float& x, float& y) {
    asm("mov.b64 {%0, %1}, %2;" : "=f"(x), "=f"(y) : "l"(v));
}

// ---------------------------------------------------------------------------
// Precompute: one thread per (g, pair p) -> writes interleaved zA/zB + v rows.
// ---------------------------------------------------------------------------
__device__ __forceinline__ float4 eff_key(const float X2[3],
                                          const float* __restrict__ Wq,
                                          const float* __restrict__ bq,
                                          const float* __restrict__ Wk) {
    const float SCALEF = 1448.1546878700492f;  // 2^10.5
    float y0 = 0.f, y1 = 0.f, y2 = 0.f, w = 0.f;
#pragma unroll
    for (int h = 0; h < 8; h++) {
        float u = fmaf(Wk[h * 3 + 0], X2[0],
                  fmaf(Wk[h * 3 + 1], X2[1], Wk[h * 3 + 2] * X2[2]));
        y0 = fmaf(Wq[h * 3 + 0], u, y0);
        y1 = fmaf(Wq[h * 3 + 1], u, y1);
        y2 = fmaf(Wq[h * 3 + 2], u, y2);
        w  = fmaf(bq[h], u, w);
    }
    return make_float4(SCALEF * y0, SCALEF * y1, SCALEF * y2, SCALEF * w);
}

__global__ void precompute_kernel(const float* __restrict__ x1,
                                  const float* __restrict__ x2,
                                  const float* __restrict__ Wq,
                                  const float* __restrict__ bq,
                                  const float* __restrict__ Wk,
                                  const float* __restrict__ Wv,
                                  const float* __restrict__ bv) {
    int i = blockIdx.x * blockDim.x + threadIdx.x;   // i = g*PAIRS + p
    if (i >= NHEAD * PAIRS) return;
    const int g = i >> 11;
    const int p = i & (PAIRS - 1);
    const int r0 = g * SEQ + 2 * p;                  // row index of t = 2p

    float X2a[3], X2b[3], X1a[3], X1b[3];
#pragma unroll
    for (int j = 0; j < 3; j++) {
        X2a[j] = x2[r0 * 3 + j];       X2b[j] = x2[(r0 + 1) * 3 + j];
        X1a[j] = x1[r0 * 3 + j];       X1b[j] = x1[(r0 + 1) * 3 + j];
    }
    const float4 za = eff_key(X2a, Wq, bq, Wk);
    const float4 zb = eff_key(X2b, Wq, bq, Wk);

    const int dst = g * PAIRS + ((p & 511) << 2) + (p >> 9);   // interleaved
    g_zA[dst] = make_float4(za.x, zb.x, za.y, zb.y);
    g_zB[dst] = make_float4(za.z, zb.z, za.w, zb.w);

#pragma unroll
    for (int h = 0; h < 8; h++) {
        g_v[(size_t)r0 * 8 + h] =
            fmaf(Wv[h * 3 + 0], X1a[0], fmaf(Wv[h * 3 + 1], X1a[1],
            fmaf(Wv[h * 3 + 2], X1a[2], bv[h])));
        g_v[(size_t)(r0 + 1) * 8 + h] =
            fmaf(Wv[h * 3 + 0], X1b[0], fmaf(Wv[h * 3 + 1], X1b[1],
            fmaf(Wv[h * 3 + 2], X1b[2], bv[h])));
    }
}

// ---------------------------------------------------------------------------
// Threefry2x32, partitionable mode: word(i) = x0^x1 of counter (0, i),
// key (0, 42). keep <=> MSB == 0.
// ---------------------------------------------------------------------------
__device__ __forceinline__ unsigned rotl32(unsigned x, int r) {
    return __funnelshift_l(x, x, r);
}
__device__ __forceinline__ unsigned threefry_word(unsigned idx) {
    const unsigned K1 = 42u;
    const unsigned K2 = 0x1BD11BF0u;
    unsigned x0 = 0u;
    unsigned x1 = idx + K1;
#define TF_R(r)  { x0 += x1; x1 = rotl32(x1, r); x1 ^= x0; }
#define TF_G(a,b,c,d,j0,j1) TF_R(a) TF_R(b) TF_R(c) TF_R(d) x0 += (j0); x1 += (j1);
    TF_G(13, 15, 26,  6, K1,       K2 + 1u)
    TF_G(17, 29, 16, 24, K2,       0u + 2u)
    TF_G(13, 15, 26,  6, 0u,       K1 + 3u)
    TF_G(17, 29, 16, 24, K1,       K2 + 4u)
    TF_G(13, 15, 26,  6, K2,       0u + 5u)
#undef TF_G
#undef TF_R
    return x0 ^ x1;
}

// Re-score a local t (0..1023) for quad lane q from interleaved smem.
__device__ __forceinline__ float score_at(const float4* __restrict__ zs, int q,
                                          int tloc, float a, float b, float c) {
    const int p   = tloc >> 1;
    const int idx = (p << 2) + q;
    const float4 A = zs[idx];
    const float4 B = zs[PAIRS + idx];
    const bool odd = (tloc & 1);
    const float zx = odd ? A.y : A.x;
    const float zy = odd ? A.w : A.z;
    const float zz = odd ? B.y : B.x;
    const float zw = odd ? B.w : B.z;
    return fmaf(a, zx, fmaf(b, zy, fmaf(c, zz, zw)));
}

// ---------------------------------------------------------------------------
// Main kernel: 4-lane quad per (g, s) row; lane q scans t in [q*1024,(q+1)*1024).
// Phase 1 (hot): scores + running max + EMIT qualifying t's (u16 -> smem).
// Phase 2 (cold, lane-parallel): re-score buffered t's, exp/threefry/V.
// Then quad shfl-merge. Block = 256 thr = 64 rows; smem = 64 KB z + 8 KB buf.
// ---------------------------------------------------------------------------
__global__ void __launch_bounds__(256) attn_kernel(const float* __restrict__ x1,
                                                   float* __restrict__ out) {
    extern __shared__ char smem_raw[];
    float4* zs = reinterpret_cast<float4*>(smem_raw);             // 4096 float4
    unsigned short* tb = reinterpret_cast<unsigned short*>(smem_raw + 65536);
    const int g = blockIdx.y;

    for (int i = threadIdx.x; i < PAIRS; i += blockDim.x) {
        zs[i]         = g_zA[g * PAIRS + i];   // linear copy keeps interleave
        zs[PAIRS + i] = g_zB[g * PAIRS + i];
    }
    __syncthreads();

    const int q   = threadIdx.x & 3;                       // quad lane
    const int s   = blockIdx.x * 64 + (threadIdx.x >> 2);  // row within head
    const int row = g * SEQ + s;

    const float a = x1[row * 3 + 0];
    const float b = x1[row * 3 + 1];
    const float c = x1[row * 3 + 2];
    const unsigned long long aa = pack2(a, a);
    const unsigned long long bb = pack2(b, b);
    const unsigned long long cc = pack2(c, c);

    const unsigned rowbase = ((unsigned)row << 12) + (unsigned)(q << 10);
    const float* vg = g_v + ((size_t)g * SEQ + (size_t)(q << 10)) * DH;

    unsigned short* mybuf = tb + threadIdx.x * CAP;
    int cnt = 0;

    const ulonglong2* ZA = reinterpret_cast<const ulonglong2*>(zs) + q;
    const ulonglong2* ZB = ZA + PAIRS;

    float m = -3.0e38f;

    // ---------------- Phase 1: scan, running max, emit ----------------
    for (int p = 0; p < 512; p += 4) {         // 8 t's per iteration
        const ulonglong2 A0 = ZA[(p + 0) << 2], B0 = ZB[(p + 0) << 2];
        const ulonglong2 A1 = ZA[(p + 1) << 2], B1 = ZB[(p + 1) << 2];
        const ulonglong2 A2 = ZA[(p + 2) << 2], B2 = ZB[(p + 2) << 2];
        const ulonglong2 A3 = ZA[(p + 3) << 2], B3 = ZB[(p + 3) << 2];
        const unsigned long long S0 = fma2(aa, A0.x, fma2(bb, A0.y, fma2(cc, B0.x, B0.y)));
        const unsigned long long S1 = fma2(aa, A1.x, fma2(bb, A1.y, fma2(cc, B1.x, B1.y)));
        const unsigned long long S2 = fma2(aa, A2.x, fma2(bb, A2.y, fma2(cc, B2.x, B2.y)));
        const unsigned long long S3 = fma2(aa, A3.x, fma2(bb, A3.y, fma2(cc, B3.x, B3.y)));
        float s0, s1, s2, s3, s4, s5, s6, s7;
        unpack2(S0, s0, s1);
        unpack2(S1, s2, s3);
        unpack2(S2, s4, s5);
        unpack2(S3, s6, s7);
        const float pm = fmaxf(fmaxf(fmaxf(s0, s1), fmaxf(s2, s3)),
                               fmaxf(fmaxf(s4, s5), fmaxf(s6, s7)));

        if (pm > m - WIN) {                    // running-window superset test
            m = fmaxf(m, pm);
            const float sv[8] = {s0, s1, s2, s3, s4, s5, s6, s7};
#pragma unroll
            for (int j = 0; j < 8; j++) {
                if (sv[j] > m - WIN) {
                    if (cnt == CAP) {
                        // prune: drop entries that fell out of the window
                        int k = 0;
                        for (int i2 = 0; i2 < CAP; i2++) {
                            const int tl = mybuf[i2];
                            if (score_at(zs, q, tl, a, b, c) > m - WIN)
                                mybuf[k++] = (unsigned short)tl;
                        }
                        cnt = k;
                        if (cnt == CAP) cnt = CAP - 1;   // ~impossible; keep newest
                    }
                    mybuf[cnt++] = (unsigned short)(2 * p + j);
                }
            }
        }
    }

    // ---------------- Phase 2: process deferred entries (lane-parallel) ----
    const float M = m;
    float l = 0.0f;
    float acc0 = 0.f, acc1 = 0.f, acc2 = 0.f, acc3 = 0.f;
    float acc4 = 0.f, acc5 = 0.f, acc6 = 0.f, acc7 = 0.f;
    for (int i = 0; i < cnt; i++) {
        const int tloc = mybuf[i];
        const float sc = score_at(zs, q, tloc, a, b, c);
        if (sc > M - WIN) {
            const float e = __expf(sc - M);
            l += e;                                   // denominator: mask-free
            const unsigned wbits = threefry_word(rowbase + (unsigned)tloc);
            if (!(wbits & 0x80000000u)) {             // keep (u < 0.5)
                const float4* vp =
                    reinterpret_cast<const float4*>(vg + (size_t)tloc * DH);
                const float4 va = vp[0];
                const float4 vb = vp[1];
                acc0 = fmaf(e, va.x, acc0);
                acc1 = fmaf(e, va.y, acc1);
                acc2 = fmaf(e, va.z, acc2);
                acc3 = fmaf(e, va.w, acc3);
                acc4 = fmaf(e, vb.x, acc4);
                acc5 = fmaf(e, vb.y, acc5);
                acc6 = fmaf(e, vb.z, acc6);
                acc7 = fmaf(e, vb.w, acc7);
            }
        }
    }

    // ---- merge the 4 partial states within the quad ----
    float Mq = m;
    Mq = fmaxf(Mq, __shfl_xor_sync(0xffffffffu, Mq, 1));
    Mq = fmaxf(Mq, __shfl_xor_sync(0xffffffffu, Mq, 2));
    const float f = __expf(m - Mq);
    l *= f;
    acc0 *= f; acc1 *= f; acc2 *= f; acc3 *= f;
    acc4 *= f; acc5 *= f; acc6 *= f; acc7 *= f;
#pragma unroll
    for (int d = 1; d <= 2; d <<= 1) {
        l    += __shfl_xor_sync(0xffffffffu, l,    d);
        acc0 += __shfl_xor_sync(0xffffffffu, acc0, d);
        acc1 += __shfl_xor_sync(0xffffffffu, acc1, d);
        acc2 += __shfl_xor_sync(0xffffffffu, acc2, d);
        acc3 += __shfl_xor_sync(0xffffffffu, acc3, d);
        acc4 += __shfl_xor_sync(0xffffffffu, acc4, d);
        acc5 += __shfl_xor_sync(0xffffffffu, acc5, d);
        acc6 += __shfl_xor_sync(0xffffffffu, acc6, d);
        acc7 += __shfl_xor_sync(0xffffffffu, acc7, d);
    }

    // out = (2 / l) * acc ; lane q writes components [2q, 2q+1] (coalesced)
    const float inv = 2.0f / l;
    const float oc[8] = {acc0 * inv, acc1 * inv, acc2 * inv, acc3 * inv,
                         acc4 * inv, acc5 * inv, acc6 * inv, acc7 * inv};
    float2* op = reinterpret_cast<float2*>(out + (size_t)row * DH);
    op[q] = make_float2(oc[2 * q], oc[2 * q + 1]);
}

// ---------------------------------------------------------------------------
extern "C" void kernel_launch(void* const* d_in, const int* in_sizes, int n_in,
                              void* d_out, int out_size) {
    const float* x1 = (const float*)d_in[0];
    const float* x2 = (const float*)d_in[1];
    const float* Wq = (const float*)d_in[2];
    const float* bq = (const float*)d_in[3];
    const float* Wk = (const float*)d_in[4];
    // d_in[5] = bk: per-row constant -> cancels in softmax
    const float* Wv = (const float*)d_in[6];
    const float* bv = (const float*)d_in[7];
    float* out = (float*)d_out;

    precompute_kernel<<<(NHEAD * PAIRS + 255) / 256, 256>>>(x1, x2, Wq, bq, Wk, Wv, bv);

    const int smem = 2 * PAIRS * (int)sizeof(float4)          // 64 KB z
                   + 256 * CAP * (int)sizeof(unsigned short); // 8 KB buffers
    cudaFuncSetAttribute(attn_kernel, cudaFuncAttributeMaxDynamicSharedMemorySize, smem);
    dim3 grid(SEQ / 64, NHEAD);
    attn_kernel<<<grid, 256, smem>>>(x1, out);
}